// round 1
// baseline (speedup 1.0000x reference)
#include <cuda_runtime.h>
#include <math.h>

#define BB 64
#define CINN 64
#define COUTT 128
#define NPIX 1024
#define TC 4

typedef unsigned long long ull;

__device__ float g_psum[COUTT * BB];
__device__ float g_psumsq[COUTT * BB];
__device__ float g_scale[COUTT];
__device__ float g_shift[COUTT];

__device__ __forceinline__ void fma2(ull &acc, ull a, ull b) {
    asm("fma.rn.f32x2 %0, %1, %2, %0;" : "+l"(acc) : "l"(a), "l"(b));
}

// floor((a)/3) for a >= -24
__device__ __forceinline__ int fd3(int a) { return (a + 24) / 3 - 8; }

// Fused: per-CTA (b, 4-cout tile): 9-tap 1x1 GEMM into SMEM, then gather+sum+maxpool,
// write pre-BN result to out, emit per-(co,b) partial sums for BN.
__global__ void __launch_bounds__(512, 1)
fused_kernel(const float* __restrict__ x, const int* __restrict__ hh,
             const int* __restrict__ wwp, const float* __restrict__ weight,
             const float* __restrict__ bias, float* __restrict__ out)
{
    extern __shared__ float smem[];
    float*  Ys  = smem;                        // 36864 floats (9*4*1024), written post-GEMM
    float*  Xs  = smem;                        // aliases first 16384 floats during GEMM
    float2* Ws2 = (float2*)(smem + 36864);     // 3072 float2 (4 co * 64 cin * 12-pad taps)

    const int tid    = threadIdx.x;
    const int b      = blockIdx.y;
    const int co0    = blockIdx.x * TC;
    const int co_l   = tid >> 7;
    const int lane128 = tid & 127;

    // ---- load weights as duplicated f32 pairs (for f32x2 broadcast multiply) ----
    for (int i = tid; i < TC * CINN * 9; i += 512) {
        int c   = i / (CINN * 9);
        int r   = i - c * (CINN * 9);
        int ci  = r / 9;
        int tap = r - ci * 9;
        float wv = weight[(co0 + c) * (CINN * 9) + ci * 9 + tap];
        Ws2[(c * CINN + ci) * 12 + tap] = make_float2(wv, wv);
    }

    // ---- GEMM phase: Y[tap][co_l][pix] = sum_cin W * x ----
    ull acc[9][4];
#pragma unroll
    for (int t = 0; t < 9; t++)
#pragma unroll
        for (int j = 0; j < 4; j++) acc[t][j] = 0ull;

    const int g0 = lane128 * 4;   // 4 consecutive pixels
    const int g1 = g0 + 512;      // second half

    for (int chunk = 0; chunk < 4; chunk++) {
        __syncthreads();  // protect Xs reuse (and Ws2 visibility on first iter)
        const float4* xg  = (const float4*)(x + (size_t)b * CINN * NPIX + chunk * 16 * NPIX);
        float4*       xs4 = (float4*)Xs;
#pragma unroll
        for (int j = 0; j < 8; j++) xs4[tid + 512 * j] = xg[tid + 512 * j];
        __syncthreads();
#pragma unroll 4
        for (int ci = 0; ci < 16; ci++) {
            int cing = chunk * 16 + ci;
            ulonglong2 xa = *(const ulonglong2*)&Xs[ci * NPIX + g0];
            ulonglong2 xb = *(const ulonglong2*)&Xs[ci * NPIX + g1];
            const ull* wp = (const ull*)&Ws2[(co_l * CINN + cing) * 12];
#pragma unroll
            for (int tap = 0; tap < 9; tap++) {
                ull wq = wp[tap];
                fma2(acc[tap][0], xa.x, wq);
                fma2(acc[tap][1], xa.y, wq);
                fma2(acc[tap][2], xb.x, wq);
                fma2(acc[tap][3], xb.y, wq);
            }
        }
    }
    __syncthreads();  // all Xs reads done; Ys may overwrite the aliased region
#pragma unroll
    for (int tap = 0; tap < 9; tap++) {
        ulonglong2 va; va.x = acc[tap][0]; va.y = acc[tap][1];
        *(ulonglong2*)&Ys[(tap * TC + co_l) * NPIX + g0] = va;
        ulonglong2 vb; vb.x = acc[tap][2]; vb.y = acc[tap][3];
        *(ulonglong2*)&Ys[(tap * TC + co_l) * NPIX + g1] = vb;
    }
    __syncthreads();

    // ---- per-sample offset tables (uniform across CTA) ----
    int dh = 96 / hh[b];  if (dh < 1) dh = 1;
    int dw = 96 / wwp[b]; if (dw < 1) dw = 1;

    int  rv[3][2];
    bool rsel[3][3];
    int  dc[3][3];
#pragma unroll
    for (int k = 0; k < 3; k++) {
        int d0 = fd3(0 + (k - 1) * dh);
        int d1 = fd3(1 + (k - 1) * dh);
        int d2 = fd3(2 + (k - 1) * dh);
        rv[k][0] = d0; rv[k][1] = d2;
        rsel[k][0] = false;
        rsel[k][1] = (d1 != d0);
        rsel[k][2] = (d2 != d0);
#pragma unroll
        for (int s = 0; s < 3; s++) dc[k][s] = fd3(s + (k - 1) * dw);
    }

    const float bias_v = bias[co0 + co_l];
    float lsum = 0.f, lsq = 0.f;

    // ---- combine: 8 pooled outputs per thread (lane-stride-1 for conflict-free LDS) ----
#pragma unroll 1
    for (int j = 0; j < 8; j++) {
        int pix = lane128 + (j << 7);
        int py  = pix >> 5;
        int px  = pix & 31;

        float RS[3][2][3];
#pragma unroll
        for (int ki = 0; ki < 3; ki++) {
#pragma unroll
            for (int v = 0; v < 2; v++) {
                int  row = py + rv[ki][v];
                bool rok = (unsigned)row < 32u;
                int  rb  = row * 32;
#pragma unroll
                for (int s = 0; s < 3; s++) {
                    float a = 0.f;
#pragma unroll
                    for (int kj = 0; kj < 3; kj++) {
                        int col = px + dc[kj][s];
                        if (rok && (unsigned)col < 32u)
                            a += Ys[((ki * 3 + kj) * TC + co_l) * NPIX + rb + col];
                    }
                    RS[ki][v][s] = a;
                }
            }
        }
        float m = -INFINITY;
#pragma unroll
        for (int r = 0; r < 3; r++) {
#pragma unroll
            for (int s = 0; s < 3; s++) {
                float v0 = rsel[0][r] ? RS[0][1][s] : RS[0][0][s];
                float v1 = rsel[1][r] ? RS[1][1][s] : RS[1][0][s];
                float v2 = rsel[2][r] ? RS[2][1][s] : RS[2][0][s];
                float cv = bias_v + v0 + v1 + v2;
                m = fmaxf(m, cv);
            }
        }
        out[((size_t)b * COUTT + co0 + co_l) * NPIX + pix] = m;
        lsum += m;
        lsq  += m * m;
    }

    // ---- deterministic per-(co,b) partial sums for BN ----
#pragma unroll
    for (int o = 16; o > 0; o >>= 1) {
        lsum += __shfl_xor_sync(0xFFFFFFFFu, lsum, o);
        lsq  += __shfl_xor_sync(0xFFFFFFFFu, lsq,  o);
    }
    __syncthreads();                 // done reading Ys/Ws2
    float* red = (float*)Ws2;        // reuse weight region: 16 warps * 2 floats
    int warp = tid >> 5;
    if ((tid & 31) == 0) { red[warp * 2] = lsum; red[warp * 2 + 1] = lsq; }
    __syncthreads();
    if (tid < TC) {
        int c = tid;
        float s = red[(4 * c + 0) * 2] + red[(4 * c + 1) * 2] +
                  red[(4 * c + 2) * 2] + red[(4 * c + 3) * 2];
        float q = red[(4 * c + 0) * 2 + 1] + red[(4 * c + 1) * 2 + 1] +
                  red[(4 * c + 2) * 2 + 1] + red[(4 * c + 3) * 2 + 1];
        g_psum  [(co0 + c) * BB + b] = s;
        g_psumsq[(co0 + c) * BB + b] = q;
    }
}

__global__ void stats_kernel(const float* __restrict__ gamma,
                             const float* __restrict__ beta)
{
    int c = threadIdx.x;  // 128 threads
    float s = 0.f, q = 0.f;
#pragma unroll 8
    for (int i = 0; i < BB; i++) { s += g_psum[c * BB + i]; q += g_psumsq[c * BB + i]; }
    const float inv = 1.0f / 65536.0f;
    float mean = s * inv;
    float var  = q * inv - mean * mean;
    float sc   = gamma[c] * rsqrtf(var + 1e-5f);
    g_scale[c] = sc;
    g_shift[c] = beta[c] - mean * sc;
}

__global__ void __launch_bounds__(1024)
apply_kernel(float* __restrict__ out)
{
    int i = blockIdx.x * 1024 + threadIdx.x;  // float4 index; grid covers 2097152 exactly
    int c = (i >> 8) & 127;                   // 256 float4 per (b,co) plane
    float4 v = ((float4*)out)[i];
    float sc = g_scale[c], sh = g_shift[c];
    v.x = fmaxf(fmaf(v.x, sc, sh), 0.f);
    v.y = fmaxf(fmaf(v.y, sc, sh), 0.f);
    v.z = fmaxf(fmaf(v.z, sc, sh), 0.f);
    v.w = fmaxf(fmaf(v.w, sc, sh), 0.f);
    ((float4*)out)[i] = v;
}

extern "C" void kernel_launch(void* const* d_in, const int* in_sizes, int n_in,
                              void* d_out, int out_size)
{
    const float* x      = (const float*)d_in[0];
    const int*   h      = (const int*)  d_in[1];
    const int*   w      = (const int*)  d_in[2];
    const float* weight = (const float*)d_in[3];
    const float* bias   = (const float*)d_in[4];
    const float* gamma  = (const float*)d_in[5];
    const float* beta   = (const float*)d_in[6];
    float* out = (float*)d_out;

    const int shmem = 36864 * 4 + 3072 * 8;  // 172032 bytes
    cudaFuncSetAttribute(fused_kernel, cudaFuncAttributeMaxDynamicSharedMemorySize, shmem);

    dim3 grid(COUTT / TC, BB);  // (32, 64)
    fused_kernel<<<grid, 512, shmem>>>(x, h, w, weight, bias, out);
    stats_kernel<<<1, 128>>>(gamma, beta);
    apply_kernel<<<2048, 1024>>>(out);
}